// round 9
// baseline (speedup 1.0000x reference)
#include <cuda_runtime.h>
#include <cuda_bf16.h>
#include <cstdint>

#define NODES 8192
#define IN_DIM 512
#define HID 128
#define OUT_DIM 64

// ---------------------------------------------------------------------------
// Scratch (device globals — allocation is forbidden)
// ---------------------------------------------------------------------------
__device__ __nv_bfloat16 g_Sh[(size_t)NODES * NODES];   // 128 MB
__device__ __nv_bfloat16 g_Sl[(size_t)NODES * NODES];   // 128 MB
__device__ __nv_bfloat16 g_Ah[(size_t)NODES * IN_DIM];
__device__ __nv_bfloat16 g_Al[(size_t)NODES * IN_DIM];
__device__ __nv_bfloat16 g_Bh[(size_t)HID * NODES];
__device__ __nv_bfloat16 g_Bl[(size_t)HID * NODES];
__device__ float g_Y0[NODES * HID];
__device__ float g_Y1[NODES * HID];
__device__ float g_P[2 * NODES * HID];   // split-K partials (slice0 | slice1)
__device__ float g_X1[NODES * HID];
__device__ float g_X2[NODES * HID];

// ---------------------------------------------------------------------------
// PTX helpers (base sm_103-safe only: cp.async, ldmatrix, mma.sync)
// ---------------------------------------------------------------------------
__device__ __forceinline__ uint32_t smem_u32(const void* p) {
    uint32_t a;
    asm("{ .reg .u64 t; cvta.to.shared.u64 t, %1; cvt.u32.u64 %0, t; }"
        : "=r"(a) : "l"(p));
    return a;
}

#define SW128(off) ((off) ^ (((off) >> 3) & 0x70))

__device__ __forceinline__ void cp16(uint32_t saddr, const void* g) {
    asm volatile("cp.async.cg.shared.global [%0], [%1], 16;" :: "r"(saddr), "l"(g));
}
#define CP_COMMIT() asm volatile("cp.async.commit_group;" ::: "memory")
#define CP_WAIT0()  asm volatile("cp.async.wait_group 0;" ::: "memory")
#define CP_WAIT1()  asm volatile("cp.async.wait_group 1;" ::: "memory")

#define LDSM_X4(r, addr)                                                        \
    asm volatile("ldmatrix.sync.aligned.m8n8.x4.shared.b16 {%0,%1,%2,%3}, [%4];" \
                 : "=r"((r)[0]), "=r"((r)[1]), "=r"((r)[2]), "=r"((r)[3])        \
                 : "r"(addr))

#define MMA16816(d, a, b)                                                        \
    asm volatile(                                                                \
        "mma.sync.aligned.m16n8k16.row.col.f32.bf16.bf16.f32 "                   \
        "{%0,%1,%2,%3}, {%4,%5,%6,%7}, {%8,%9}, {%0,%1,%2,%3};"                  \
        : "+f"((d)[0]), "+f"((d)[1]), "+f"((d)[2]), "+f"((d)[3])                 \
        : "r"((a)[0]), "r"((a)[1]), "r"((a)[2]), "r"((a)[3]),                    \
          "r"((b)[0]), "r"((b)[1]))

// ---------------------------------------------------------------------------
// bf16 hi/lo split (same layout)
// ---------------------------------------------------------------------------
__global__ void split_kernel(const float4* __restrict__ in,
                             uint2* __restrict__ hi, uint2* __restrict__ lo, int n4) {
    int i = blockIdx.x * blockDim.x + threadIdx.x;
    if (i >= n4) return;
    float4 v = in[i];
    __nv_bfloat16 h0 = __float2bfloat16(v.x), h1 = __float2bfloat16(v.y);
    __nv_bfloat16 h2 = __float2bfloat16(v.z), h3 = __float2bfloat16(v.w);
    __nv_bfloat16 l0 = __float2bfloat16(v.x - __bfloat162float(h0));
    __nv_bfloat16 l1 = __float2bfloat16(v.y - __bfloat162float(h1));
    __nv_bfloat16 l2 = __float2bfloat16(v.z - __bfloat162float(h2));
    __nv_bfloat16 l3 = __float2bfloat16(v.w - __bfloat162float(h3));
    uint2 uh, ul;
    uh.x = (uint32_t)__bfloat16_as_ushort(h0) | ((uint32_t)__bfloat16_as_ushort(h1) << 16);
    uh.y = (uint32_t)__bfloat16_as_ushort(h2) | ((uint32_t)__bfloat16_as_ushort(h3) << 16);
    ul.x = (uint32_t)__bfloat16_as_ushort(l0) | ((uint32_t)__bfloat16_as_ushort(l1) << 16);
    ul.y = (uint32_t)__bfloat16_as_ushort(l2) | ((uint32_t)__bfloat16_as_ushort(l3) << 16);
    hi[i] = uh;
    lo[i] = ul;
}

// Transpose + split: in[R,C] fp32 row-major -> hi/lo[C,R] bf16 row-major
__global__ void tsplit_kernel(const float* __restrict__ in,
                              __nv_bfloat16* __restrict__ hi,
                              __nv_bfloat16* __restrict__ lo, int R, int C) {
    __shared__ float t[32][33];
    int bx = blockIdx.x * 32;  // col base
    int by = blockIdx.y * 32;  // row base
    int tx = threadIdx.x, ty = threadIdx.y;
#pragma unroll
    for (int j = 0; j < 32; j += 8)
        t[ty + j][tx] = in[(size_t)(by + ty + j) * C + bx + tx];
    __syncthreads();
#pragma unroll
    for (int j = 0; j < 32; j += 8) {
        float v = t[tx][ty + j];
        __nv_bfloat16 h = __float2bfloat16(v);
        __nv_bfloat16 l = __float2bfloat16(v - __bfloat162float(h));
        size_t o = (size_t)(bx + ty + j) * R + by + tx;
        hi[o] = h;
        lo[o] = l;
    }
}

// Sum two split-K partials, emit fp32 sum (original layout) + transposed hi/lo
__global__ void tsplit2_kernel(const float* __restrict__ in0,
                               const float* __restrict__ in1,
                               __nv_bfloat16* __restrict__ hi,
                               __nv_bfloat16* __restrict__ lo,
                               float* __restrict__ sum, int R, int C) {
    __shared__ float t[32][33];
    int bx = blockIdx.x * 32;  // col base
    int by = blockIdx.y * 32;  // row base
    int tx = threadIdx.x, ty = threadIdx.y;
#pragma unroll
    for (int j = 0; j < 32; j += 8) {
        size_t idx = (size_t)(by + ty + j) * C + bx + tx;
        float v = in0[idx] + in1[idx];
        t[ty + j][tx] = v;
        sum[idx] = v;
    }
    __syncthreads();
#pragma unroll
    for (int j = 0; j < 32; j += 8) {
        float v = t[tx][ty + j];
        __nv_bfloat16 h = __float2bfloat16(v);
        __nv_bfloat16 l = __float2bfloat16(v - __bfloat162float(h));
        size_t o = (size_t)(bx + ty + j) * R + by + tx;
        hi[o] = h;
        lo[o] = l;
    }
}

// ---------------------------------------------------------------------------
// Split-GEMM on mma.sync (HMMA): C[M,BN] = A[M,K] @ B[BN,K]^T
//   D = Ah*Bh + Ah*Bl + Al*Bh (fp32 accum).
//   BM=128, BK=64, 8 warps (4 x 2), each warp 32 x (BN/2). 2-stage cp.async.
//   KS-way split-K over blockIdx.y; slice k writes C + k*M*BN.
// ---------------------------------------------------------------------------
template <int BN, int KS>
__global__ void __launch_bounds__(256, 1)
gemm_mma_kernel(const __nv_bfloat16* __restrict__ Ah, const __nv_bfloat16* __restrict__ Al,
                const __nv_bfloat16* __restrict__ Bh, const __nv_bfloat16* __restrict__ Bl,
                float* __restrict__ C, int K) {
    constexpr int BM = 128, BK = 64;
    constexpr uint32_t ATILE = BM * BK * 2;           // 16384 B per matrix
    constexpr uint32_t BTILE = BN * BK * 2;           // 16384 / 8192 B
    constexpr uint32_t STAGE = 2 * ATILE + 2 * BTILE; // Ah,Al,Bh,Bl

    extern __shared__ __align__(1024) char smem[];
    const uint32_t sb = smem_u32(smem);

    const int tid = threadIdx.x;
    const int lane = tid & 31, wid = tid >> 5;
    const int warp_m = wid & 3;        // 4 m-blocks of 32 rows
    const int warp_n = wid >> 2;       // 2 n-blocks of WTN cols
    constexpr int WTN = BN / 2;        // 64 or 32
    constexpr int NTILES = WTN / 8;    // 8 or 4
    constexpr int NPAIR = NTILES / 2;  // 4 or 2
    const int row0 = blockIdx.x * BM;

    const int Kper = K / KS;
    const int kbase = blockIdx.y * Kper;
    C += (size_t)blockIdx.y * ((size_t)gridDim.x * BM) * BN;

    float acc[2][NTILES][4];
#pragma unroll
    for (int i = 0; i < 2; i++)
#pragma unroll
        for (int j = 0; j < NTILES; j++)
#pragma unroll
            for (int k = 0; k < 4; k++) acc[i][j][k] = 0.0f;

    const int nst = Kper >> 6;

    auto load_stage = [&](int s) {
        const uint32_t base = sb + (uint32_t)(s & 1) * STAGE;
        const int k0 = kbase + s * BK;
        // A hi+lo: 128 rows x 8 granules of 16B
#pragma unroll
        for (int i = 0; i < 4; i++) {
            int id = tid + i * 256;
            int r = id >> 3, kg = id & 7;
            uint32_t so = SW128((uint32_t)(r * 128 + kg * 16));
            size_t go = (size_t)(row0 + r) * K + k0 + kg * 8;
            cp16(base + so, Ah + go);
            cp16(base + ATILE + so, Al + go);
        }
        // B hi+lo: BN rows x 8 granules
#pragma unroll
        for (int i = 0; i < (BN * 8) / 256; i++) {
            int id = tid + i * 256;
            int r = id >> 3, kg = id & 7;
            uint32_t so = SW128((uint32_t)(r * 128 + kg * 16));
            size_t go = (size_t)r * K + k0 + kg * 8;
            cp16(base + 2 * ATILE + so, Bh + go);
            cp16(base + 2 * ATILE + BTILE + so, Bl + go);
        }
    };

    const int a_row = warp_m * 32 + (lane & 15);
    const int a_colb = (lane >> 4) << 4;
    const int b_row = warp_n * WTN + (lane & 7) + ((lane >> 4) << 3);
    const int b_colb = ((lane >> 3) & 1) << 4;

    load_stage(0);
    CP_COMMIT();

    for (int s = 0; s < nst; s++) {
        if (s + 1 < nst) {
            load_stage(s + 1);
            CP_COMMIT();
            CP_WAIT1();
        } else {
            CP_WAIT0();
        }
        __syncthreads();

        const uint32_t base = sb + (uint32_t)(s & 1) * STAGE;
#pragma unroll
        for (int ks = 0; ks < 4; ks++) {
            uint32_t ah[2][4], al[2][4];
#pragma unroll
            for (int mt = 0; mt < 2; mt++) {
                uint32_t off =
                    SW128((uint32_t)((a_row + mt * 16) * 128 + ks * 32 + a_colb));
                LDSM_X4(ah[mt], base + off);
                LDSM_X4(al[mt], base + ATILE + off);
            }
            uint32_t bh[NTILES][2], bl[NTILES][2];
#pragma unroll
            for (int p = 0; p < NPAIR; p++) {
                uint32_t off =
                    SW128((uint32_t)((b_row + p * 16) * 128 + ks * 32 + b_colb));
                uint32_t th[4], tl[4];
                LDSM_X4(th, base + 2 * ATILE + off);
                LDSM_X4(tl, base + 2 * ATILE + BTILE + off);
                bh[2 * p][0] = th[0]; bh[2 * p][1] = th[1];
                bh[2 * p + 1][0] = th[2]; bh[2 * p + 1][1] = th[3];
                bl[2 * p][0] = tl[0]; bl[2 * p][1] = tl[1];
                bl[2 * p + 1][0] = tl[2]; bl[2 * p + 1][1] = tl[3];
            }
#pragma unroll
            for (int mt = 0; mt < 2; mt++)
#pragma unroll
                for (int nt = 0; nt < NTILES; nt++) {
                    MMA16816(acc[mt][nt], ah[mt], bh[nt]);
                    MMA16816(acc[mt][nt], ah[mt], bl[nt]);
                    MMA16816(acc[mt][nt], al[mt], bh[nt]);
                }
        }
        __syncthreads();
    }

    const int m_base = row0 + warp_m * 32;
    const int n_base = warp_n * WTN;
#pragma unroll
    for (int mt = 0; mt < 2; mt++) {
#pragma unroll
        for (int nt = 0; nt < NTILES; nt++) {
            int r = m_base + mt * 16 + (lane >> 2);
            int c = n_base + nt * 8 + (lane & 3) * 2;
            *reinterpret_cast<float2*>(&C[(size_t)r * BN + c]) =
                make_float2(acc[mt][nt][0], acc[mt][nt][1]);
            *reinterpret_cast<float2*>(&C[(size_t)(r + 8) * BN + c]) =
                make_float2(acc[mt][nt][2], acc[mt][nt][3]);
        }
    }
}

// ---------------------------------------------------------------------------
// Combine: out = act(h0*Y0 + h1*Y1 + h2*(Y2a+Y2b) + b[col]), vectorized
// ---------------------------------------------------------------------------
__global__ void combine_kernel(int total4, int N,
                               const float4* __restrict__ Y0,
                               const float4* __restrict__ Y1,
                               const float4* __restrict__ Y2a,
                               const float4* __restrict__ Y2b,
                               const float* __restrict__ h,
                               const float* __restrict__ b,
                               float4* __restrict__ out, int do_relu) {
    int i = blockIdx.x * blockDim.x + threadIdx.x;
    if (i >= total4) return;
    int j = (i * 4) & (N - 1);
    float h0 = h[0], h1 = h[1], h2 = h[2];
    float4 a = Y0[i], c = Y1[i], da = Y2a[i], db = Y2b[i];
    float4 r;
    r.x = fmaf(h0, a.x, fmaf(h1, c.x, fmaf(h2, da.x + db.x, b[j])));
    r.y = fmaf(h0, a.y, fmaf(h1, c.y, fmaf(h2, da.y + db.y, b[j + 1])));
    r.z = fmaf(h0, a.z, fmaf(h1, c.z, fmaf(h2, da.z + db.z, b[j + 2])));
    r.w = fmaf(h0, a.w, fmaf(h1, c.w, fmaf(h2, da.w + db.w, b[j + 3])));
    if (do_relu) {
        r.x = fmaxf(r.x, 0.f); r.y = fmaxf(r.y, 0.f);
        r.z = fmaxf(r.z, 0.f); r.w = fmaxf(r.w, 0.f);
    }
    out[i] = r;
}

// ---------------------------------------------------------------------------
// Host orchestration (all GEMMs KS=2; partials reduced by tsplit2/combine)
// ---------------------------------------------------------------------------
static void run_split(const float* x, __nv_bfloat16* hi, __nv_bfloat16* lo, size_t n) {
    int n4 = (int)(n / 4);
    split_kernel<<<(n4 + 255) / 256, 256>>>((const float4*)x, (uint2*)hi, (uint2*)lo, n4);
}

static void run_tsplit(const float* in, __nv_bfloat16* hi, __nv_bfloat16* lo, int R, int C) {
    dim3 grid(C / 32, R / 32), block(32, 8);
    tsplit_kernel<<<grid, block>>>(in, hi, lo, R, C);
}

static void run_tsplit2(const float* in0, const float* in1, __nv_bfloat16* hi,
                        __nv_bfloat16* lo, float* sum, int R, int C) {
    dim3 grid(C / 32, R / 32), block(32, 8);
    tsplit2_kernel<<<grid, block>>>(in0, in1, hi, lo, sum, R, C);
}

template <int BN, int KS>
static void run_gemm(const __nv_bfloat16* Ah, const __nv_bfloat16* Al,
                     const __nv_bfloat16* Bh, const __nv_bfloat16* Bl,
                     float* C, int K) {
    constexpr uint32_t STAGE = 2 * (128 * 64 * 2) + 2 * (BN * 64 * 2);
    constexpr uint32_t smem_bytes = 2 * STAGE;
    cudaFuncSetAttribute(gemm_mma_kernel<BN, KS>,
                         cudaFuncAttributeMaxDynamicSharedMemorySize, smem_bytes);
    dim3 grid(NODES / 128, KS);
    gemm_mma_kernel<BN, KS><<<grid, 256, smem_bytes>>>(Ah, Al, Bh, Bl, C, K);
}

static void run_combine(const float* Y0, const float* Y1, const float* Y2a,
                        const float* Y2b, const float* h, const float* b,
                        float* out, int N, int relu) {
    int total4 = NODES * N / 4;
    combine_kernel<<<(total4 + 255) / 256, 256>>>(
        total4, N, (const float4*)Y0, (const float4*)Y1, (const float4*)Y2a,
        (const float4*)Y2b, h, b, (float4*)out, relu);
}

extern "C" void kernel_launch(void* const* d_in, const int* in_sizes, int n_in,
                              void* d_out, int out_size) {
    const float* S  = (const float*)d_in[0];
    const float* X  = (const float*)d_in[1];
    const float* W1 = (const float*)d_in[2];
    const float* h1 = (const float*)d_in[3];
    const float* b1 = (const float*)d_in[4];
    const float* W2 = (const float*)d_in[5];
    const float* h2 = (const float*)d_in[6];
    const float* b2 = (const float*)d_in[7];
    const float* W3 = (const float*)d_in[8];
    const float* h3 = (const float*)d_in[9];
    const float* b3 = (const float*)d_in[10];
    float* out = (float*)d_out;

    __nv_bfloat16 *Sh, *Sl, *Ah, *Al, *Bh, *Bl;
    float *Y0, *Y1, *P, *X1, *X2;
    cudaGetSymbolAddress((void**)&Sh, g_Sh);
    cudaGetSymbolAddress((void**)&Sl, g_Sl);
    cudaGetSymbolAddress((void**)&Ah, g_Ah);
    cudaGetSymbolAddress((void**)&Al, g_Al);
    cudaGetSymbolAddress((void**)&Bh, g_Bh);
    cudaGetSymbolAddress((void**)&Bl, g_Bl);
    cudaGetSymbolAddress((void**)&Y0, g_Y0);
    cudaGetSymbolAddress((void**)&Y1, g_Y1);
    cudaGetSymbolAddress((void**)&P, g_P);
    cudaGetSymbolAddress((void**)&X1, g_X1);
    cudaGetSymbolAddress((void**)&X2, g_X2);

    float* P1_128 = P + (size_t)NODES * HID;      // slice-1 base for BN=128
    float* P1_64  = P + (size_t)NODES * OUT_DIM;  // slice-1 base for BN=64

    // S -> bf16 hi/lo (recomputed every launch; caching would break determinism)
    run_split(S, Sh, Sl, (size_t)NODES * NODES);

    // -------- layer 1 (N=128, ReLU) --------
    run_split(X, Ah, Al, (size_t)NODES * IN_DIM);
    run_tsplit(W1, Bh, Bl, IN_DIM, HID);
    run_gemm<HID, 2>(Ah, Al, Bh, Bl, P, IN_DIM);     // P|P1 = X@W1 partials
    run_tsplit2(P, P1_128, Bh, Bl, Y0, NODES, HID);  // Y0 = sum; split Y0^T
    run_gemm<HID, 2>(Sh, Sl, Bh, Bl, P, NODES);      // P|P1 = S@Y0 partials
    run_tsplit2(P, P1_128, Bh, Bl, Y1, NODES, HID);  // Y1 = sum; split Y1^T
    run_gemm<HID, 2>(Sh, Sl, Bh, Bl, P, NODES);      // P|P1 = S@Y1 partials
    run_combine(Y0, Y1, P, P1_128, h1, b1, X1, HID, 1);

    // -------- layer 2 (N=128, ReLU) --------
    run_split(X1, Ah, Al, (size_t)NODES * HID);
    run_tsplit(W2, Bh, Bl, HID, HID);
    run_gemm<HID, 2>(Ah, Al, Bh, Bl, P, HID);
    run_tsplit2(P, P1_128, Bh, Bl, Y0, NODES, HID);
    run_gemm<HID, 2>(Sh, Sl, Bh, Bl, P, NODES);
    run_tsplit2(P, P1_128, Bh, Bl, Y1, NODES, HID);
    run_gemm<HID, 2>(Sh, Sl, Bh, Bl, P, NODES);
    run_combine(Y0, Y1, P, P1_128, h2, b2, X2, HID, 1);

    // -------- layer 3 (N=64, identity) --------
    run_split(X2, Ah, Al, (size_t)NODES * HID);
    run_tsplit(W3, Bh, Bl, HID, OUT_DIM);
    run_gemm<OUT_DIM, 2>(Ah, Al, Bh, Bl, P, HID);
    run_tsplit2(P, P1_64, Bh, Bl, Y0, NODES, OUT_DIM);
    run_gemm<OUT_DIM, 2>(Sh, Sl, Bh, Bl, P, NODES);
    run_tsplit2(P, P1_64, Bh, Bl, Y1, NODES, OUT_DIM);
    run_gemm<OUT_DIM, 2>(Sh, Sl, Bh, Bl, P, NODES);
    run_combine(Y0, Y1, P, P1_64, h3, b3, out, OUT_DIM, 0);
}

// round 12
// speedup vs baseline: 1.3965x; 1.3965x over previous
#include <cuda_runtime.h>
#include <cuda_fp16.h>
#include <cstdint>

#define NODES 8192
#define IN_DIM 512
#define HID 128
#define OUT_DIM 64

// ---------------------------------------------------------------------------
// Scratch (device globals — allocation is forbidden)
// ---------------------------------------------------------------------------
__device__ __half g_Sh[(size_t)NODES * NODES];          // 128 MB (hi only)
__device__ __half g_Ah[(size_t)NODES * IN_DIM];         // A-side hi (X / X1 / X2)
__device__ __half g_Bh[(size_t)HID * NODES];            // B-side hi (Y^T / W^T)
__device__ __half g_Bl[(size_t)HID * NODES];            // B-side lo
__device__ float g_Y0[NODES * HID];
__device__ float g_Y1[NODES * HID];
__device__ float g_P[2 * NODES * HID];   // split-K partials (slice0 | slice1)
__device__ float g_X1[NODES * HID];
__device__ float g_X2[NODES * HID];

// ---------------------------------------------------------------------------
// PTX helpers (base sm_103-safe only: cp.async, ldmatrix, mma.sync)
// ---------------------------------------------------------------------------
__device__ __forceinline__ uint32_t smem_u32(const void* p) {
    uint32_t a;
    asm("{ .reg .u64 t; cvta.to.shared.u64 t, %1; cvt.u32.u64 %0, t; }"
        : "=r"(a) : "l"(p));
    return a;
}

#define SW128(off) ((off) ^ (((off) >> 3) & 0x70))

__device__ __forceinline__ void cp16(uint32_t saddr, const void* g) {
    asm volatile("cp.async.cg.shared.global [%0], [%1], 16;" :: "r"(saddr), "l"(g));
}
#define CP_COMMIT() asm volatile("cp.async.commit_group;" ::: "memory")
#define CP_WAIT0()  asm volatile("cp.async.wait_group 0;" ::: "memory")
#define CP_WAIT1()  asm volatile("cp.async.wait_group 1;" ::: "memory")

#define LDSM_X4(r, addr)                                                        \
    asm volatile("ldmatrix.sync.aligned.m8n8.x4.shared.b16 {%0,%1,%2,%3}, [%4];" \
                 : "=r"((r)[0]), "=r"((r)[1]), "=r"((r)[2]), "=r"((r)[3])        \
                 : "r"(addr))

#define MMA16816F16(d, a, b)                                                     \
    asm volatile(                                                                \
        "mma.sync.aligned.m16n8k16.row.col.f32.f16.f16.f32 "                     \
        "{%0,%1,%2,%3}, {%4,%5,%6,%7}, {%8,%9}, {%0,%1,%2,%3};"                  \
        : "+f"((d)[0]), "+f"((d)[1]), "+f"((d)[2]), "+f"((d)[3])                 \
        : "r"((a)[0]), "r"((a)[1]), "r"((a)[2]), "r"((a)[3]),                    \
          "r"((b)[0]), "r"((b)[1]))

// ---------------------------------------------------------------------------
// fp16 hi-only split (A-side operands: S, X, X1, X2)
// ---------------------------------------------------------------------------
__global__ void split_h_kernel(const float4* __restrict__ in,
                               uint2* __restrict__ hi, int n4) {
    int i = blockIdx.x * blockDim.x + threadIdx.x;
    if (i >= n4) return;
    float4 v = in[i];
    __half2 p0 = __floats2half2_rn(v.x, v.y);
    __half2 p1 = __floats2half2_rn(v.z, v.w);
    uint2 u;
    u.x = *reinterpret_cast<uint32_t*>(&p0);
    u.y = *reinterpret_cast<uint32_t*>(&p1);
    hi[i] = u;
}

// Transpose + hi/lo split: in[R,C] fp32 row-major -> hi/lo[C,R] fp16 row-major
__global__ void tsplit_kernel(const float* __restrict__ in,
                              __half* __restrict__ hi,
                              __half* __restrict__ lo, int R, int C) {
    __shared__ float t[32][33];
    int bx = blockIdx.x * 32;  // col base
    int by = blockIdx.y * 32;  // row base
    int tx = threadIdx.x, ty = threadIdx.y;
#pragma unroll
    for (int j = 0; j < 32; j += 8)
        t[ty + j][tx] = in[(size_t)(by + ty + j) * C + bx + tx];
    __syncthreads();
#pragma unroll
    for (int j = 0; j < 32; j += 8) {
        float v = t[tx][ty + j];
        __half h = __float2half_rn(v);
        __half l = __float2half_rn(v - __half2float(h));
        size_t o = (size_t)(bx + ty + j) * R + by + tx;
        hi[o] = h;
        lo[o] = l;
    }
}

// Sum two split-K partials, emit fp32 sum + transposed fp16 hi/lo
__global__ void tsplit2_kernel(const float* __restrict__ in0,
                               const float* __restrict__ in1,
                               __half* __restrict__ hi,
                               __half* __restrict__ lo,
                               float* __restrict__ sum, int R, int C) {
    __shared__ float t[32][33];
    int bx = blockIdx.x * 32;  // col base
    int by = blockIdx.y * 32;  // row base
    int tx = threadIdx.x, ty = threadIdx.y;
#pragma unroll
    for (int j = 0; j < 32; j += 8) {
        size_t idx = (size_t)(by + ty + j) * C + bx + tx;
        float v = in0[idx] + in1[idx];
        t[ty + j][tx] = v;
        sum[idx] = v;
    }
    __syncthreads();
#pragma unroll
    for (int j = 0; j < 32; j += 8) {
        float v = t[tx][ty + j];
        __half h = __float2half_rn(v);
        __half l = __float2half_rn(v - __half2float(h));
        size_t o = (size_t)(bx + ty + j) * R + by + tx;
        hi[o] = h;
        lo[o] = l;
    }
}

// ---------------------------------------------------------------------------
// 2-pass fp16 GEMM on mma.sync: C[M,BN] = A[M,K] @ B[BN,K]^T
//   D = Ah@Bh + Ah@Bl (fp32 accum). A is hi-only; B is hi+lo.
//   BM=64, BK=64, 8 warps (2 x 4), 2-stage cp.async, SW128 smem.
//   KS-way split-K over blockIdx.y; slice k writes C + k*M*BN.
// ---------------------------------------------------------------------------
template <int BN, int KS>
__global__ void __launch_bounds__(256, 2)
gemm_mma_kernel(const __half* __restrict__ Ah,
                const __half* __restrict__ Bh, const __half* __restrict__ Bl,
                float* __restrict__ C, int K) {
    constexpr int BM = 64, BK = 64;
    constexpr uint32_t ATILE = BM * BK * 2;           // 8192 B
    constexpr uint32_t BTILE = BN * BK * 2;           // 16384 / 8192 B
    constexpr uint32_t STAGE = ATILE + 2 * BTILE;     // Ah, Bh, Bl

    extern __shared__ __align__(1024) char smem[];
    const uint32_t sb = smem_u32(smem);

    const int tid = threadIdx.x;
    const int lane = tid & 31, wid = tid >> 5;
    const int warp_m = wid & 1;        // 2 m-blocks of 32 rows
    const int warp_n = wid >> 1;       // 4 n-blocks of WTN cols
    constexpr int WTN = BN / 4;        // 32 or 16
    constexpr int NTILES = WTN / 8;    // 4 or 2
    constexpr int NPAIR = NTILES / 2;  // 2 or 1
    const int row0 = blockIdx.x * BM;

    const int Kper = K / KS;
    const int kbase = blockIdx.y * Kper;
    C += (size_t)blockIdx.y * ((size_t)gridDim.x * BM) * BN;

    float acc[2][NTILES][4];
#pragma unroll
    for (int i = 0; i < 2; i++)
#pragma unroll
        for (int j = 0; j < NTILES; j++)
#pragma unroll
            for (int k = 0; k < 4; k++) acc[i][j][k] = 0.0f;

    const int nst = Kper >> 6;

    auto load_stage = [&](int s) {
        const uint32_t base = sb + (uint32_t)(s & 1) * STAGE;
        const int k0 = kbase + s * BK;
        // A hi: 64 rows x 8 granules of 16B
#pragma unroll
        for (int i = 0; i < 2; i++) {
            int id = tid + i * 256;
            int r = id >> 3, kg = id & 7;
            uint32_t so = SW128((uint32_t)(r * 128 + kg * 16));
            size_t go = (size_t)(row0 + r) * K + k0 + kg * 8;
            cp16(base + so, Ah + go);
        }
        // B hi+lo: BN rows x 8 granules
#pragma unroll
        for (int i = 0; i < (BN * 8) / 256; i++) {
            int id = tid + i * 256;
            int r = id >> 3, kg = id & 7;
            uint32_t so = SW128((uint32_t)(r * 128 + kg * 16));
            size_t go = (size_t)r * K + k0 + kg * 8;
            cp16(base + ATILE + so, Bh + go);
            cp16(base + ATILE + BTILE + so, Bl + go);
        }
    };

    const int a_row = warp_m * 32 + (lane & 15);
    const int a_colb = (lane >> 4) << 4;
    const int b_row = warp_n * WTN + (lane & 7) + ((lane >> 4) << 3);
    const int b_colb = ((lane >> 3) & 1) << 4;

    load_stage(0);
    CP_COMMIT();

    for (int s = 0; s < nst; s++) {
        if (s + 1 < nst) {
            load_stage(s + 1);
            CP_COMMIT();
            CP_WAIT1();
        } else {
            CP_WAIT0();
        }
        __syncthreads();

        const uint32_t base = sb + (uint32_t)(s & 1) * STAGE;
#pragma unroll
        for (int ks = 0; ks < 4; ks++) {
            uint32_t ah[2][4];
#pragma unroll
            for (int mt = 0; mt < 2; mt++) {
                uint32_t off =
                    SW128((uint32_t)((a_row + mt * 16) * 128 + ks * 32 + a_colb));
                LDSM_X4(ah[mt], base + off);
            }
            uint32_t bh[NTILES][2], bl[NTILES][2];
#pragma unroll
            for (int p = 0; p < NPAIR; p++) {
                uint32_t off =
                    SW128((uint32_t)((b_row + p * 16) * 128 + ks * 32 + b_colb));
                uint32_t th[4], tl[4];
                LDSM_X4(th, base + ATILE + off);
                LDSM_X4(tl, base + ATILE + BTILE + off);
                bh[2 * p][0] = th[0]; bh[2 * p][1] = th[1];
                bh[2 * p + 1][0] = th[2]; bh[2 * p + 1][1] = th[3];
                bl[2 * p][0] = tl[0]; bl[2 * p][1] = tl[1];
                bl[2 * p + 1][0] = tl[2]; bl[2 * p + 1][1] = tl[3];
            }
#pragma unroll
            for (int mt = 0; mt < 2; mt++)
#pragma unroll
                for (int nt = 0; nt < NTILES; nt++) {
                    MMA16816F16(acc[mt][nt], ah[mt], bh[nt]);
                    MMA16816F16(acc[mt][nt], ah[mt], bl[nt]);
                }
        }
        __syncthreads();
    }

    const int m_base = row0 + warp_m * 32;
    const int n_base = warp_n * WTN;
#pragma unroll
    for (int mt = 0; mt < 2; mt++) {
#pragma unroll
        for (int nt = 0; nt < NTILES; nt++) {
            int r = m_base + mt * 16 + (lane >> 2);
            int c = n_base + nt * 8 + (lane & 3) * 2;
            *reinterpret_cast<float2*>(&C[(size_t)r * BN + c]) =
                make_float2(acc[mt][nt][0], acc[mt][nt][1]);
            *reinterpret_cast<float2*>(&C[(size_t)(r + 8) * BN + c]) =
                make_float2(acc[mt][nt][2], acc[mt][nt][3]);
        }
    }
}

// ---------------------------------------------------------------------------
// Combine: out = act(h0*Y0 + h1*Y1 + h2*(Y2a+Y2b) + b[col]), vectorized
// ---------------------------------------------------------------------------
__global__ void combine_kernel(int total4, int N,
                               const float4* __restrict__ Y0,
                               const float4* __restrict__ Y1,
                               const float4* __restrict__ Y2a,
                               const float4* __restrict__ Y2b,
                               const float* __restrict__ h,
                               const float* __restrict__ b,
                               float4* __restrict__ out, int do_relu) {
    int i = blockIdx.x * blockDim.x + threadIdx.x;
    if (i >= total4) return;
    int j = (i * 4) & (N - 1);
    float h0 = h[0], h1 = h[1], h2 = h[2];
    float4 a = Y0[i], c = Y1[i], da = Y2a[i], db = Y2b[i];
    float4 r;
    r.x = fmaf(h0, a.x, fmaf(h1, c.x, fmaf(h2, da.x + db.x, b[j])));
    r.y = fmaf(h0, a.y, fmaf(h1, c.y, fmaf(h2, da.y + db.y, b[j + 1])));
    r.z = fmaf(h0, a.z, fmaf(h1, c.z, fmaf(h2, da.z + db.z, b[j + 2])));
    r.w = fmaf(h0, a.w, fmaf(h1, c.w, fmaf(h2, da.w + db.w, b[j + 3])));
    if (do_relu) {
        r.x = fmaxf(r.x, 0.f); r.y = fmaxf(r.y, 0.f);
        r.z = fmaxf(r.z, 0.f); r.w = fmaxf(r.w, 0.f);
    }
    out[i] = r;
}

// ---------------------------------------------------------------------------
// Host orchestration (all GEMMs KS=2; partials reduced by tsplit2/combine)
// ---------------------------------------------------------------------------
static void run_split_h(const float* x, __half* hi, size_t n) {
    int n4 = (int)(n / 4);
    split_h_kernel<<<(n4 + 255) / 256, 256>>>((const float4*)x, (uint2*)hi, n4);
}

static void run_tsplit(const float* in, __half* hi, __half* lo, int R, int C) {
    dim3 grid(C / 32, R / 32), block(32, 8);
    tsplit_kernel<<<grid, block>>>(in, hi, lo, R, C);
}

static void run_tsplit2(const float* in0, const float* in1, __half* hi,
                        __half* lo, float* sum, int R, int C) {
    dim3 grid(C / 32, R / 32), block(32, 8);
    tsplit2_kernel<<<grid, block>>>(in0, in1, hi, lo, sum, R, C);
}

template <int BN, int KS>
static void run_gemm(const __half* Ah, const __half* Bh, const __half* Bl,
                     float* C, int K) {
    constexpr uint32_t STAGE = (64 * 64 * 2) + 2 * (BN * 64 * 2);
    constexpr uint32_t smem_bytes = 2 * STAGE;
    cudaFuncSetAttribute(gemm_mma_kernel<BN, KS>,
                         cudaFuncAttributeMaxDynamicSharedMemorySize, smem_bytes);
    dim3 grid(NODES / 64, KS);
    gemm_mma_kernel<BN, KS><<<grid, 256, smem_bytes>>>(Ah, Bh, Bl, C, K);
}

static void run_combine(const float* Y0, const float* Y1, const float* Y2a,
                        const float* Y2b, const float* h, const float* b,
                        float* out, int N, int relu) {
    int total4 = NODES * N / 4;
    combine_kernel<<<(total4 + 255) / 256, 256>>>(
        total4, N, (const float4*)Y0, (const float4*)Y1, (const float4*)Y2a,
        (const float4*)Y2b, h, b, (float4*)out, relu);
}

extern "C" void kernel_launch(void* const* d_in, const int* in_sizes, int n_in,
                              void* d_out, int out_size) {
    const float* S  = (const float*)d_in[0];
    const float* X  = (const float*)d_in[1];
    const float* W1 = (const float*)d_in[2];
    const float* h1 = (const float*)d_in[3];
    const float* b1 = (const float*)d_in[4];
    const float* W2 = (const float*)d_in[5];
    const float* h2 = (const float*)d_in[6];
    const float* b2 = (const float*)d_in[7];
    const float* W3 = (const float*)d_in[8];
    const float* h3 = (const float*)d_in[9];
    const float* b3 = (const float*)d_in[10];
    float* out = (float*)d_out;

    __half *Sh, *Ah, *Bh, *Bl;
    float *Y0, *Y1, *P, *X1, *X2;
    cudaGetSymbolAddress((void**)&Sh, g_Sh);
    cudaGetSymbolAddress((void**)&Ah, g_Ah);
    cudaGetSymbolAddress((void**)&Bh, g_Bh);
    cudaGetSymbolAddress((void**)&Bl, g_Bl);
    cudaGetSymbolAddress((void**)&Y0, g_Y0);
    cudaGetSymbolAddress((void**)&Y1, g_Y1);
    cudaGetSymbolAddress((void**)&P, g_P);
    cudaGetSymbolAddress((void**)&X1, g_X1);
    cudaGetSymbolAddress((void**)&X2, g_X2);

    float* P1_128 = P + (size_t)NODES * HID;      // slice-1 base for BN=128
    float* P1_64  = P + (size_t)NODES * OUT_DIM;  // slice-1 base for BN=64

    // S -> fp16 hi (recomputed every launch; caching would break determinism)
    run_split_h(S, Sh, (size_t)NODES * NODES);

    // -------- layer 1 (N=128, ReLU) --------
    run_split_h(X, Ah, (size_t)NODES * IN_DIM);
    run_tsplit(W1, Bh, Bl, IN_DIM, HID);
    run_gemm<HID, 2>(Ah, Bh, Bl, P, IN_DIM);         // P|P1 = X@W1 partials
    run_tsplit2(P, P1_128, Bh, Bl, Y0, NODES, HID);  // Y0 = sum; split Y0^T
    run_gemm<HID, 2>(Sh, Bh, Bl, P, NODES);          // P|P1 = S@Y0 partials
    run_tsplit2(P, P1_128, Bh, Bl, Y1, NODES, HID);  // Y1 = sum; split Y1^T
    run_gemm<HID, 2>(Sh, Bh, Bl, P, NODES);          // P|P1 = S@Y1 partials
    run_combine(Y0, Y1, P, P1_128, h1, b1, X1, HID, 1);

    // -------- layer 2 (N=128, ReLU) --------
    run_split_h(X1, Ah, (size_t)NODES * HID);
    run_tsplit(W2, Bh, Bl, HID, HID);
    run_gemm<HID, 2>(Ah, Bh, Bl, P, HID);
    run_tsplit2(P, P1_128, Bh, Bl, Y0, NODES, HID);
    run_gemm<HID, 2>(Sh, Bh, Bl, P, NODES);
    run_tsplit2(P, P1_128, Bh, Bl, Y1, NODES, HID);
    run_gemm<HID, 2>(Sh, Bh, Bl, P, NODES);
    run_combine(Y0, Y1, P, P1_128, h2, b2, X2, HID, 1);

    // -------- layer 3 (N=64, identity) --------
    run_split_h(X2, Ah, (size_t)NODES * HID);
    run_tsplit(W3, Bh, Bl, HID, OUT_DIM);
    run_gemm<OUT_DIM, 2>(Ah, Bh, Bl, P, HID);
    run_tsplit2(P, P1_64, Bh, Bl, Y0, NODES, OUT_DIM);
    run_gemm<OUT_DIM, 2>(Sh, Bh, Bl, P, NODES);
    run_tsplit2(P, P1_64, Bh, Bl, Y1, NODES, OUT_DIM);
    run_gemm<OUT_DIM, 2>(Sh, Bh, Bl, P, NODES);
    run_combine(Y0, Y1, P, P1_64, h3, b3, out, OUT_DIM, 0);
}